// round 13
// baseline (speedup 1.0000x reference)
#include <cuda_runtime.h>
#include <cuda_fp16.h>
#include <cstdint>

#define N_NODES 100000
#define N_EDGES 1600000
#define DIM 64
#define BN_EPS 1e-5f
#define CAP 64          // bucket capacity; Poisson(16) max deg over 100k ~ 45

// ---------------- scratch (no allocation allowed; zero-init at load) --------
__device__ __half g_hh[N_NODES * DIM];     // 12.8 MB: h = x @ W (unscaled, fp16)
__device__ __half g_outh[N_NODES * DIM];   // 12.8 MB: pre-BN aggregate, fp16
__device__ float g_dinv[N_NODES];
__device__ int   g_cursor[N_NODES];        // in-degree after fill; reset by normrelu
__device__ int   g_col[N_NODES * CAP];     // 25.6 MB bucketed CSR
__device__ float g_colsum[DIM];            // reset by fillgemm (block 0) each replay
__device__ float g_colsumsq[DIM];

// ---------------- kernels ----------------

// Merged kernel: all 782 blocks fill the bucketed CSR (8 edges/thread) AND
// compute a 128-row tile of h = x @ W via fp16 HMMA (m16n8k16, fp32 accum).
__global__ void __launch_bounds__(256) fillgemm_kernel(const int* __restrict__ src,
                                                       const int* __restrict__ dst,
                                                       const float* __restrict__ x,
                                                       const float* __restrict__ W) {
    if (blockIdx.x == 0 && threadIdx.x < DIM) {
        g_colsum[threadIdx.x] = 0.0f;
        g_colsumsq[threadIdx.x] = 0.0f;
    }
    int tid = threadIdx.x;

    // ---- fill part ----
    int i = blockIdx.x * 256 + tid;
    if (i < N_EDGES / 8) {
        int4 sa = ((const int4*)src)[2 * i];
        int4 sb = ((const int4*)src)[2 * i + 1];
        int4 da = ((const int4*)dst)[2 * i];
        int4 db = ((const int4*)dst)[2 * i + 1];
        int p0 = atomicAdd(&g_cursor[da.x], 1);
        int p1 = atomicAdd(&g_cursor[da.y], 1);
        int p2 = atomicAdd(&g_cursor[da.z], 1);
        int p3 = atomicAdd(&g_cursor[da.w], 1);
        int p4 = atomicAdd(&g_cursor[db.x], 1);
        int p5 = atomicAdd(&g_cursor[db.y], 1);
        int p6 = atomicAdd(&g_cursor[db.z], 1);
        int p7 = atomicAdd(&g_cursor[db.w], 1);
        if (p0 < CAP) g_col[da.x * CAP + p0] = sa.x;
        if (p1 < CAP) g_col[da.y * CAP + p1] = sa.y;
        if (p2 < CAP) g_col[da.z * CAP + p2] = sa.z;
        if (p3 < CAP) g_col[da.w * CAP + p3] = sa.w;
        if (p4 < CAP) g_col[db.x * CAP + p4] = sb.x;
        if (p5 < CAP) g_col[db.y * CAP + p5] = sb.y;
        if (p6 < CAP) g_col[db.z * CAP + p6] = sb.z;
        if (p7 < CAP) g_col[db.w * CAP + p7] = sb.w;
    }

    // ---- gemm part: 128 rows/block, fp16 HMMA ----
    __shared__ __half xs[128 * 72];   // 72-half row stride (LDSM conflict-free)
    __shared__ __half ws[64 * 72];

    int row0 = blockIdx.x * 128;
    for (int j = tid; j < 128 * 32; j += 256) {
        int r = j >> 5, c2 = j & 31;            // half2 column
        int gr = row0 + r;
        float2 v = (gr < N_NODES) ? ((const float2*)x)[gr * 32 + c2]
                                  : make_float2(0.f, 0.f);
        *(__half2*)&xs[r * 72 + c2 * 2] = __floats2half2_rn(v.x, v.y);
    }
    for (int j = tid; j < 64 * 32; j += 256) {
        float2 v = ((const float2*)W)[j];
        int k = j >> 5, n2 = j & 31;
        *(__half2*)&ws[k * 72 + n2 * 2] = __floats2half2_rn(v.x, v.y);
    }
    __syncthreads();

    int lane = tid & 31;
    int warp = tid >> 5;
    int warp_m = warp * 16;

    unsigned xs_base = (unsigned)__cvta_generic_to_shared(xs);
    unsigned ws_base = (unsigned)__cvta_generic_to_shared(ws);
    unsigned a_base = xs_base + (warp_m + (lane & 15)) * 144u + (lane >> 4) * 16u;
    unsigned b_base = ws_base + (lane & 15) * 144u;

    float acc[8][4];
#pragma unroll
    for (int nt = 0; nt < 8; nt++)
#pragma unroll
        for (int c = 0; c < 4; c++) acc[nt][c] = 0.f;

#pragma unroll
    for (int kc = 0; kc < 4; kc++) {
        unsigned ra0, ra1, ra2, ra3;
        asm volatile("ldmatrix.sync.aligned.m8n8.x4.shared.b16 {%0,%1,%2,%3}, [%4];"
                     : "=r"(ra0), "=r"(ra1), "=r"(ra2), "=r"(ra3)
                     : "r"(a_base + kc * 32u));
        unsigned bk = b_base + (unsigned)(kc * 16 * 144);
#pragma unroll
        for (int nt = 0; nt < 8; nt++) {
            unsigned rb0, rb1;
            asm volatile("ldmatrix.sync.aligned.m8n8.x2.trans.shared.b16 {%0,%1}, [%2];"
                         : "=r"(rb0), "=r"(rb1)
                         : "r"(bk + nt * 16u));
            asm volatile("mma.sync.aligned.m16n8k16.row.col.f32.f16.f16.f32 "
                         "{%0,%1,%2,%3}, {%4,%5,%6,%7}, {%8,%9}, {%0,%1,%2,%3};"
                         : "+f"(acc[nt][0]), "+f"(acc[nt][1]),
                           "+f"(acc[nt][2]), "+f"(acc[nt][3])
                         : "r"(ra0), "r"(ra1), "r"(ra2), "r"(ra3), "r"(rb0), "r"(rb1));
        }
    }

    int r0 = row0 + warp_m + (lane >> 2);
    int cb = 2 * (lane & 3);
#pragma unroll
    for (int nt = 0; nt < 8; nt++) {
        if (r0 < N_NODES)
            *(__half2*)&g_hh[r0 * 64 + nt * 8 + cb] =
                __floats2half2_rn(acc[nt][0], acc[nt][1]);
        if (r0 + 8 < N_NODES)
            *(__half2*)&g_hh[(r0 + 8) * 64 + nt * 8 + cb] =
                __floats2half2_rn(acc[nt][2], acc[nt][3]);
    }
}

// dinv = rsqrt(deg+1) from the freshly-built counts
__global__ void __launch_bounds__(256) dinv_kernel() {
    int i = blockIdx.x * 256 + threadIdx.x;
    if (i < N_NODES) g_dinv[i] = rsqrtf((float)(g_cursor[i] + 1));
}

// CSR gather: outh[d] = dinv[d]*(dinv[d]*h[d] + sum_j dinv[s_j]*h[s_j]) in fp16;
// fused BN stats. Uniform int4 col loads; fp16 h rows; x8 unroll; 1-wave grid.
__global__ void __launch_bounds__(256) gather_kernel() {
    int lane = threadIdx.x & 31;
    int wib = threadIdx.x >> 5;
    int wglobal = blockIdx.x * 8 + wib;
    int wtotal = gridDim.x * 8;
    const __half2* __restrict__ hs2 = (const __half2*)g_hh;

    float s0 = 0.f, s1 = 0.f, q0 = 0.f, q1 = 0.f;

    for (int d = wglobal; d < N_NODES; d += wtotal) {
        int cnt = g_cursor[d];
        float dv = rsqrtf((float)(cnt + 1));
        if (cnt > CAP) cnt = CAP;
        int hb = d * (DIM / 2);
        float2 self = __half22float2(hs2[hb + lane]);   // cols 2l, 2l+1
        float ax = self.x * dv, ay = self.y * dv;
        float bx = 0.f, by = 0.f;
        const int* __restrict__ col = g_col + d * CAP;
        int jj = 0;
        for (; jj + 7 < cnt; jj += 8) {
            int4 cA = *(const int4*)(col + jj);
            int4 cB = *(const int4*)(col + jj + 4);
            float nA = g_dinv[cA.x], nB = g_dinv[cA.y];
            float nC = g_dinv[cA.z], nD = g_dinv[cA.w];
            float nE = g_dinv[cB.x], nF = g_dinv[cB.y];
            float nG = g_dinv[cB.z], nH = g_dinv[cB.w];
            float2 vA = __half22float2(hs2[cA.x * (DIM / 2) + lane]);
            float2 vB = __half22float2(hs2[cA.y * (DIM / 2) + lane]);
            float2 vC = __half22float2(hs2[cA.z * (DIM / 2) + lane]);
            float2 vD = __half22float2(hs2[cA.w * (DIM / 2) + lane]);
            float2 vE = __half22float2(hs2[cB.x * (DIM / 2) + lane]);
            float2 vF = __half22float2(hs2[cB.y * (DIM / 2) + lane]);
            float2 vG = __half22float2(hs2[cB.z * (DIM / 2) + lane]);
            float2 vH = __half22float2(hs2[cB.w * (DIM / 2) + lane]);
            ax = fmaf(vA.x, nA, ax);  ay = fmaf(vA.y, nA, ay);
            bx = fmaf(vB.x, nB, bx);  by = fmaf(vB.y, nB, by);
            ax = fmaf(vC.x, nC, ax);  ay = fmaf(vC.y, nC, ay);
            bx = fmaf(vD.x, nD, bx);  by = fmaf(vD.y, nD, by);
            ax = fmaf(vE.x, nE, ax);  ay = fmaf(vE.y, nE, ay);
            bx = fmaf(vF.x, nF, bx);  by = fmaf(vF.y, nF, by);
            ax = fmaf(vG.x, nG, ax);  ay = fmaf(vG.y, nG, ay);
            bx = fmaf(vH.x, nH, bx);  by = fmaf(vH.y, nH, by);
        }
        for (; jj + 3 < cnt; jj += 4) {
            int4 cA = *(const int4*)(col + jj);
            float nA = g_dinv[cA.x], nB = g_dinv[cA.y];
            float nC = g_dinv[cA.z], nD = g_dinv[cA.w];
            float2 vA = __half22float2(hs2[cA.x * (DIM / 2) + lane]);
            float2 vB = __half22float2(hs2[cA.y * (DIM / 2) + lane]);
            float2 vC = __half22float2(hs2[cA.z * (DIM / 2) + lane]);
            float2 vD = __half22float2(hs2[cA.w * (DIM / 2) + lane]);
            ax = fmaf(vA.x, nA, ax);  ay = fmaf(vA.y, nA, ay);
            bx = fmaf(vB.x, nB, bx);  by = fmaf(vB.y, nB, by);
            ax = fmaf(vC.x, nC, ax);  ay = fmaf(vC.y, nC, ay);
            bx = fmaf(vD.x, nD, bx);  by = fmaf(vD.y, nD, by);
        }
        for (; jj < cnt; jj++) {
            int sA = col[jj];
            float nA = g_dinv[sA];
            float2 v = __half22float2(hs2[sA * (DIM / 2) + lane]);
            ax = fmaf(v.x, nA, ax);
            ay = fmaf(v.y, nA, ay);
        }
        float ox = (ax + bx) * dv;
        float oy = (ay + by) * dv;
        ((__half2*)g_outh)[hb + lane] = __floats2half2_rn(ox, oy);
        s0 += ox; s1 += oy;
        q0 = fmaf(ox, ox, q0); q1 = fmaf(oy, oy, q1);
    }

    __shared__ float redA[8][DIM];
    __shared__ float redB[8][DIM];
    redA[wib][lane * 2 + 0] = s0; redA[wib][lane * 2 + 1] = s1;
    redB[wib][lane * 2 + 0] = q0; redB[wib][lane * 2 + 1] = q1;
    __syncthreads();
    if (threadIdx.x < DIM) {
        int c = threadIdx.x;
        float t = 0.f, tq = 0.f;
#pragma unroll
        for (int w = 0; w < 8; w++) { t += redA[w][c]; tq += redB[w][c]; }
        atomicAdd(&g_colsum[c], t);
        atomicAdd(&g_colsumsq[c], tq);
    }
}

// out = relu(outh*scale+shift) -> fp32 d_out; BN scale/shift from global
// accumulators (bias b cancels in BN). Also resets g_cursor for next replay.
__global__ void __launch_bounds__(256) normrelu_kernel(float* __restrict__ out,
                                                       const float* __restrict__ gamma,
                                                       const float* __restrict__ beta) {
    __shared__ float sc[DIM], sh[DIM];
    if (threadIdx.x < DIM) {
        int c = threadIdx.x;
        const float invN = 1.0f / (float)N_NODES;
        float mean = g_colsum[c] * invN;
        float var = g_colsumsq[c] * invN - mean * mean;
        float istd = rsqrtf(var + BN_EPS);
        float s = gamma[c] * istd;
        sc[c] = s;
        sh[c] = beta[c] - mean * s;
    }
    __syncthreads();
    int i = blockIdx.x * 256 + threadIdx.x;
    if (i < N_NODES) g_cursor[i] = 0;
    if (i >= N_NODES * (DIM / 4)) return;
    // load 4 halves (two half2), store float4
    const __half2* oh = (const __half2*)g_outh;
    float2 lo = __half22float2(oh[i * 2]);
    float2 hi = __half22float2(oh[i * 2 + 1]);
    int c = (i & 15) * 4;
    float4 v;
    v.x = fmaxf(fmaf(lo.x, sc[c + 0], sh[c + 0]), 0.0f);
    v.y = fmaxf(fmaf(lo.y, sc[c + 1], sh[c + 1]), 0.0f);
    v.z = fmaxf(fmaf(hi.x, sc[c + 2], sh[c + 2]), 0.0f);
    v.w = fmaxf(fmaf(hi.y, sc[c + 3], sh[c + 3]), 0.0f);
    ((float4*)out)[i] = v;
}

// ---------------- launch ----------------
extern "C" void kernel_launch(void* const* d_in, const int* in_sizes, int n_in,
                              void* d_out, int out_size) {
    const float* x     = (const float*)d_in[0];
    const int*   ei    = (const int*)d_in[1];
    const float* W     = (const float*)d_in[2];
    // d_in[3] = b : cancels under BatchNorm, unused
    const float* gamma = (const float*)d_in[4];
    const float* beta  = (const float*)d_in[5];
    float* out = (float*)d_out;

    const int* src = ei;
    const int* dst = ei + N_EDGES;

    fillgemm_kernel<<<(N_NODES + 127) / 128, 256>>>(src, dst, x, W);  // 782 blocks
    dinv_kernel<<<(N_NODES + 255) / 256, 256>>>();
    gather_kernel<<<592, 256>>>();   // 148 SMs x 4 blocks = 1 wave
    normrelu_kernel<<<(N_NODES * (DIM / 4) + 255) / 256, 256>>>(out, gamma, beta);
}

// round 14
// speedup vs baseline: 1.2154x; 1.2154x over previous
#include <cuda_runtime.h>
#include <cuda_fp16.h>
#include <cstdint>

#define N_NODES 100000
#define N_EDGES 1600000
#define DIM 64
#define BN_EPS 1e-5f
#define CAP 64          // bucket capacity; Poisson(16) max deg over 100k ~ 45

// ---------------- scratch (no allocation allowed; zero-init at load) --------
__device__ __half g_hh[N_NODES * DIM];     // 12.8 MB: h = x @ W (unscaled, fp16)
__device__ __half g_outh[N_NODES * DIM];   // 12.8 MB: pre-BN aggregate, fp16
__device__ float g_dinv[N_NODES];
__device__ int   g_cursor[N_NODES];        // in-degree after fill; reset by normrelu
__device__ int   g_col[N_NODES * CAP];     // 25.6 MB bucketed CSR
__device__ float g_colsum[DIM];            // reset by fillgemm (block 0) each replay
__device__ float g_colsumsq[DIM];

// ---------------- kernels ----------------

// Merged kernel: all 782 blocks fill the bucketed CSR (8 edges/thread) AND
// compute a 128-row tile of h = x @ W via fp16 HMMA (m16n8k16, fp32 accum).
__global__ void __launch_bounds__(256) fillgemm_kernel(const int* __restrict__ src,
                                                       const int* __restrict__ dst,
                                                       const float* __restrict__ x,
                                                       const float* __restrict__ W) {
    if (blockIdx.x == 0 && threadIdx.x < DIM) {
        g_colsum[threadIdx.x] = 0.0f;
        g_colsumsq[threadIdx.x] = 0.0f;
    }
    int tid = threadIdx.x;

    // ---- fill part ----
    int i = blockIdx.x * 256 + tid;
    if (i < N_EDGES / 8) {
        int4 sa = ((const int4*)src)[2 * i];
        int4 sb = ((const int4*)src)[2 * i + 1];
        int4 da = ((const int4*)dst)[2 * i];
        int4 db = ((const int4*)dst)[2 * i + 1];
        int p0 = atomicAdd(&g_cursor[da.x], 1);
        int p1 = atomicAdd(&g_cursor[da.y], 1);
        int p2 = atomicAdd(&g_cursor[da.z], 1);
        int p3 = atomicAdd(&g_cursor[da.w], 1);
        int p4 = atomicAdd(&g_cursor[db.x], 1);
        int p5 = atomicAdd(&g_cursor[db.y], 1);
        int p6 = atomicAdd(&g_cursor[db.z], 1);
        int p7 = atomicAdd(&g_cursor[db.w], 1);
        if (p0 < CAP) g_col[da.x * CAP + p0] = sa.x;
        if (p1 < CAP) g_col[da.y * CAP + p1] = sa.y;
        if (p2 < CAP) g_col[da.z * CAP + p2] = sa.z;
        if (p3 < CAP) g_col[da.w * CAP + p3] = sa.w;
        if (p4 < CAP) g_col[db.x * CAP + p4] = sb.x;
        if (p5 < CAP) g_col[db.y * CAP + p5] = sb.y;
        if (p6 < CAP) g_col[db.z * CAP + p6] = sb.z;
        if (p7 < CAP) g_col[db.w * CAP + p7] = sb.w;
    }

    // ---- gemm part: 128 rows/block, fp16 HMMA ----
    __shared__ __half xs[128 * 72];   // 72-half row stride (LDSM conflict-free)
    __shared__ __half ws[64 * 72];

    int row0 = blockIdx.x * 128;
    for (int j = tid; j < 128 * 32; j += 256) {
        int r = j >> 5, c2 = j & 31;            // half2 column
        int gr = row0 + r;
        float2 v = (gr < N_NODES) ? ((const float2*)x)[gr * 32 + c2]
                                  : make_float2(0.f, 0.f);
        *(__half2*)&xs[r * 72 + c2 * 2] = __floats2half2_rn(v.x, v.y);
    }
    for (int j = tid; j < 64 * 32; j += 256) {
        float2 v = ((const float2*)W)[j];
        int k = j >> 5, n2 = j & 31;
        *(__half2*)&ws[k * 72 + n2 * 2] = __floats2half2_rn(v.x, v.y);
    }
    __syncthreads();

    int lane = tid & 31;
    int warp = tid >> 5;
    int warp_m = warp * 16;

    unsigned xs_base = (unsigned)__cvta_generic_to_shared(xs);
    unsigned ws_base = (unsigned)__cvta_generic_to_shared(ws);
    unsigned a_base = xs_base + (warp_m + (lane & 15)) * 144u + (lane >> 4) * 16u;
    unsigned b_base = ws_base + (lane & 15) * 144u;

    float acc[8][4];
#pragma unroll
    for (int nt = 0; nt < 8; nt++)
#pragma unroll
        for (int c = 0; c < 4; c++) acc[nt][c] = 0.f;

#pragma unroll
    for (int kc = 0; kc < 4; kc++) {
        unsigned ra0, ra1, ra2, ra3;
        asm volatile("ldmatrix.sync.aligned.m8n8.x4.shared.b16 {%0,%1,%2,%3}, [%4];"
                     : "=r"(ra0), "=r"(ra1), "=r"(ra2), "=r"(ra3)
                     : "r"(a_base + kc * 32u));
        unsigned bk = b_base + (unsigned)(kc * 16 * 144);
#pragma unroll
        for (int nt = 0; nt < 8; nt++) {
            unsigned rb0, rb1;
            asm volatile("ldmatrix.sync.aligned.m8n8.x2.trans.shared.b16 {%0,%1}, [%2];"
                         : "=r"(rb0), "=r"(rb1)
                         : "r"(bk + nt * 16u));
            asm volatile("mma.sync.aligned.m16n8k16.row.col.f32.f16.f16.f32 "
                         "{%0,%1,%2,%3}, {%4,%5,%6,%7}, {%8,%9}, {%0,%1,%2,%3};"
                         : "+f"(acc[nt][0]), "+f"(acc[nt][1]),
                           "+f"(acc[nt][2]), "+f"(acc[nt][3])
                         : "r"(ra0), "r"(ra1), "r"(ra2), "r"(ra3), "r"(rb0), "r"(rb1));
        }
    }

    int r0 = row0 + warp_m + (lane >> 2);
    int cb = 2 * (lane & 3);
#pragma unroll
    for (int nt = 0; nt < 8; nt++) {
        if (r0 < N_NODES)
            *(__half2*)&g_hh[r0 * 64 + nt * 8 + cb] =
                __floats2half2_rn(acc[nt][0], acc[nt][1]);
        if (r0 + 8 < N_NODES)
            *(__half2*)&g_hh[(r0 + 8) * 64 + nt * 8 + cb] =
                __floats2half2_rn(acc[nt][2], acc[nt][3]);
    }
}

// dinv = rsqrt(deg+1) from the freshly-built counts
__global__ void __launch_bounds__(256) dinv_kernel() {
    int i = blockIdx.x * 256 + threadIdx.x;
    if (i < N_NODES) g_dinv[i] = rsqrtf((float)(g_cursor[i] + 1));
}

// CSR gather: outh[d] = dinv[d]*(dinv[d]*h[d] + sum_j dinv[s_j]*h[s_j]) in fp16;
// fused BN stats. Uniform int4 col loads; fp16 h rows; x8 unroll.
__global__ void __launch_bounds__(256) gather_kernel() {
    int lane = threadIdx.x & 31;
    int wib = threadIdx.x >> 5;
    int wglobal = blockIdx.x * 8 + wib;
    int wtotal = gridDim.x * 8;
    const __half2* __restrict__ hs2 = (const __half2*)g_hh;

    float s0 = 0.f, s1 = 0.f, q0 = 0.f, q1 = 0.f;

    for (int d = wglobal; d < N_NODES; d += wtotal) {
        int cnt = g_cursor[d];
        float dv = rsqrtf((float)(cnt + 1));
        if (cnt > CAP) cnt = CAP;
        int hb = d * (DIM / 2);
        float2 self = __half22float2(hs2[hb + lane]);   // cols 2l, 2l+1
        float ax = self.x * dv, ay = self.y * dv;
        float bx = 0.f, by = 0.f;
        const int* __restrict__ col = g_col + d * CAP;
        int jj = 0;
        for (; jj + 7 < cnt; jj += 8) {
            int4 cA = *(const int4*)(col + jj);
            int4 cB = *(const int4*)(col + jj + 4);
            float nA = g_dinv[cA.x], nB = g_dinv[cA.y];
            float nC = g_dinv[cA.z], nD = g_dinv[cA.w];
            float nE = g_dinv[cB.x], nF = g_dinv[cB.y];
            float nG = g_dinv[cB.z], nH = g_dinv[cB.w];
            float2 vA = __half22float2(hs2[cA.x * (DIM / 2) + lane]);
            float2 vB = __half22float2(hs2[cA.y * (DIM / 2) + lane]);
            float2 vC = __half22float2(hs2[cA.z * (DIM / 2) + lane]);
            float2 vD = __half22float2(hs2[cA.w * (DIM / 2) + lane]);
            float2 vE = __half22float2(hs2[cB.x * (DIM / 2) + lane]);
            float2 vF = __half22float2(hs2[cB.y * (DIM / 2) + lane]);
            float2 vG = __half22float2(hs2[cB.z * (DIM / 2) + lane]);
            float2 vH = __half22float2(hs2[cB.w * (DIM / 2) + lane]);
            ax = fmaf(vA.x, nA, ax);  ay = fmaf(vA.y, nA, ay);
            bx = fmaf(vB.x, nB, bx);  by = fmaf(vB.y, nB, by);
            ax = fmaf(vC.x, nC, ax);  ay = fmaf(vC.y, nC, ay);
            bx = fmaf(vD.x, nD, bx);  by = fmaf(vD.y, nD, by);
            ax = fmaf(vE.x, nE, ax);  ay = fmaf(vE.y, nE, ay);
            bx = fmaf(vF.x, nF, bx);  by = fmaf(vF.y, nF, by);
            ax = fmaf(vG.x, nG, ax);  ay = fmaf(vG.y, nG, ay);
            bx = fmaf(vH.x, nH, bx);  by = fmaf(vH.y, nH, by);
        }
        for (; jj + 3 < cnt; jj += 4) {
            int4 cA = *(const int4*)(col + jj);
            float nA = g_dinv[cA.x], nB = g_dinv[cA.y];
            float nC = g_dinv[cA.z], nD = g_dinv[cA.w];
            float2 vA = __half22float2(hs2[cA.x * (DIM / 2) + lane]);
            float2 vB = __half22float2(hs2[cA.y * (DIM / 2) + lane]);
            float2 vC = __half22float2(hs2[cA.z * (DIM / 2) + lane]);
            float2 vD = __half22float2(hs2[cA.w * (DIM / 2) + lane]);
            ax = fmaf(vA.x, nA, ax);  ay = fmaf(vA.y, nA, ay);
            bx = fmaf(vB.x, nB, bx);  by = fmaf(vB.y, nB, by);
            ax = fmaf(vC.x, nC, ax);  ay = fmaf(vC.y, nC, ay);
            bx = fmaf(vD.x, nD, bx);  by = fmaf(vD.y, nD, by);
        }
        for (; jj < cnt; jj++) {
            int sA = col[jj];
            float nA = g_dinv[sA];
            float2 v = __half22float2(hs2[sA * (DIM / 2) + lane]);
            ax = fmaf(v.x, nA, ax);
            ay = fmaf(v.y, nA, ay);
        }
        float ox = (ax + bx) * dv;
        float oy = (ay + by) * dv;
        ((__half2*)g_outh)[hb + lane] = __floats2half2_rn(ox, oy);
        s0 += ox; s1 += oy;
        q0 = fmaf(ox, ox, q0); q1 = fmaf(oy, oy, q1);
    }

    __shared__ float redA[8][DIM];
    __shared__ float redB[8][DIM];
    redA[wib][lane * 2 + 0] = s0; redA[wib][lane * 2 + 1] = s1;
    redB[wib][lane * 2 + 0] = q0; redB[wib][lane * 2 + 1] = q1;
    __syncthreads();
    if (threadIdx.x < DIM) {
        int c = threadIdx.x;
        float t = 0.f, tq = 0.f;
#pragma unroll
        for (int w = 0; w < 8; w++) { t += redA[w][c]; tq += redB[w][c]; }
        atomicAdd(&g_colsum[c], t);
        atomicAdd(&g_colsumsq[c], tq);
    }
}

// out = relu(outh*scale+shift) -> fp32 d_out; BN scale/shift from global
// accumulators (bias b cancels in BN). Also resets g_cursor for next replay.
__global__ void __launch_bounds__(256) normrelu_kernel(float* __restrict__ out,
                                                       const float* __restrict__ gamma,
                                                       const float* __restrict__ beta) {
    __shared__ float sc[DIM], sh[DIM];
    if (threadIdx.x < DIM) {
        int c = threadIdx.x;
        const float invN = 1.0f / (float)N_NODES;
        float mean = g_colsum[c] * invN;
        float var = g_colsumsq[c] * invN - mean * mean;
        float istd = rsqrtf(var + BN_EPS);
        float s = gamma[c] * istd;
        sc[c] = s;
        sh[c] = beta[c] - mean * s;
    }
    __syncthreads();
    int i = blockIdx.x * 256 + threadIdx.x;
    if (i < N_NODES) g_cursor[i] = 0;
    if (i >= N_NODES * (DIM / 4)) return;
    const __half2* oh = (const __half2*)g_outh;
    float2 lo = __half22float2(oh[i * 2]);
    float2 hi = __half22float2(oh[i * 2 + 1]);
    int c = (i & 15) * 4;
    float4 v;
    v.x = fmaxf(fmaf(lo.x, sc[c + 0], sh[c + 0]), 0.0f);
    v.y = fmaxf(fmaf(lo.y, sc[c + 1], sh[c + 1]), 0.0f);
    v.z = fmaxf(fmaf(hi.x, sc[c + 2], sh[c + 2]), 0.0f);
    v.w = fmaxf(fmaf(hi.y, sc[c + 3], sh[c + 3]), 0.0f);
    ((float4*)out)[i] = v;
}

// ---------------- launch ----------------
extern "C" void kernel_launch(void* const* d_in, const int* in_sizes, int n_in,
                              void* d_out, int out_size) {
    const float* x     = (const float*)d_in[0];
    const int*   ei    = (const int*)d_in[1];
    const float* W     = (const float*)d_in[2];
    // d_in[3] = b : cancels under BatchNorm, unused
    const float* gamma = (const float*)d_in[4];
    const float* beta  = (const float*)d_in[5];
    float* out = (float*)d_out;

    const int* src = ei;
    const int* dst = ei + N_EDGES;

    fillgemm_kernel<<<(N_NODES + 127) / 128, 256>>>(src, dst, x, W);  // 782 blocks
    dinv_kernel<<<(N_NODES + 255) / 256, 256>>>();
    gather_kernel<<<2048, 256>>>();   // 8 blocks/SM occupancy; proven shape
    normrelu_kernel<<<(N_NODES * (DIM / 4) + 255) / 256, 256>>>(out, gamma, beta);
}